// round 2
// baseline (speedup 1.0000x reference)
#include <cuda_runtime.h>
#include <math.h>

#define BLOCK   128
#define KNN     16
#define HID     64
#define NPTS    65536

__global__ __launch_bounds__(BLOCK) void point_embed_kernel(
    const float* __restrict__ pos,        // [B,3,N]
    const int*   __restrict__ idx,        // [B,N,K] int32 (JAX x64 disabled)
    const float* __restrict__ dist,       // [B,N,K]
    const float* __restrict__ W,          // [10,64]
    const float* __restrict__ bias,       // [64]
    float* __restrict__ out,              // [B,N,64]
    int N)
{
    __shared__ float feat_s[10][BLOCK];

    const int t = threadIdx.x;
    const long long base_pt = (long long)blockIdx.x * BLOCK;   // global point of thread 0
    const int bb = (int)(base_pt / N);     // whole block lies in one batch (N % BLOCK == 0)
    const int n  = (int)(base_pt % N) + t;

    // ---------------- Phase 1: per-point feature (10 channels) ----------------
    const float* px = pos + (size_t)bb * 3 * N;   // batch's xyz plane
    const float x = __ldg(px + n);
    const float y = __ldg(px + N + n);
    const float z = __ldg(px + 2 * N + n);

    const int*   ip = idx  + ((size_t)bb * N + n) * KNN;
    const float* dp = dist + ((size_t)bb * N + n) * KNN;

    float mx = -INFINITY, my = -INFINITY, mz = -INFINITY;   // max neighbor
    float nx =  INFINITY, ny =  INFINITY, nz =  INFINITY;   // min neighbor
    float md = -INFINITY;                                    // max dist

    #pragma unroll
    for (int k = 0; k < KNN; k += 4) {
        int4 jj = *reinterpret_cast<const int4*>(ip + k);    // 16B aligned
        #pragma unroll
        for (int u = 0; u < 4; u++) {
            const int j = (u == 0) ? jj.x : (u == 1) ? jj.y : (u == 2) ? jj.z : jj.w;
            const float ax = __ldg(px + j);
            const float ay = __ldg(px + N + j);
            const float az = __ldg(px + 2 * N + j);
            mx = fmaxf(mx, ax);  nx = fminf(nx, ax);
            my = fmaxf(my, ay);  ny = fminf(ny, ay);
            mz = fmaxf(mz, az);  nz = fminf(nz, az);
        }
    }

    #pragma unroll
    for (int k = 0; k < KNN; k += 4) {
        float4 d4 = *reinterpret_cast<const float4*>(dp + k);  // 16B aligned
        md = fmaxf(md, fmaxf(fmaxf(d4.x, d4.y), fmaxf(d4.z, d4.w)));
    }

    feat_s[0][t] = x;
    feat_s[1][t] = y;
    feat_s[2][t] = z;
    feat_s[3][t] = mx;
    feat_s[4][t] = my;
    feat_s[5][t] = mz;
    feat_s[6][t] = x - nx;   // max(ext - nbr) = ext - min(nbr)
    feat_s[7][t] = y - ny;
    feat_s[8][t] = z - nz;
    feat_s[9][t] = md;

    __syncthreads();

    // ---------------- Phase 2: 10x64 matvec, coalesced stores ----------------
    // Thread t owns output channel h = t & 63 for points p = (t>>6) + 2*i.
    const int h = t & 63;
    float wc[10];
    #pragma unroll
    for (int c = 0; c < 10; c++) wc[c] = __ldg(W + c * HID + h);
    const float bv = __ldg(bias + h);

    float* ob = out + (size_t)base_pt * HID;
    const int p0 = t >> 6;

    #pragma unroll 8
    for (int i = 0; i < BLOCK / 2; i++) {
        const int p = p0 + 2 * i;
        float acc = bv;
        #pragma unroll
        for (int c = 0; c < 10; c++)
            acc = fmaf(feat_s[c][p], wc[c], acc);   // feat read is warp-broadcast
        ob[(size_t)p * HID + h] = fmaxf(acc, 0.0f); // warp writes 128B contiguous
    }
}

extern "C" void kernel_launch(void* const* d_in, const int* in_sizes, int n_in,
                              void* d_out, int out_size) {
    const float* pos  = (const float*)d_in[0];   // [B,3,N] f32
    const int*   idx  = (const int*)d_in[1];     // [B,N,K] i32
    const float* dist = (const float*)d_in[2];   // [B,N,K] f32
    const float* W    = (const float*)d_in[3];   // [10,64] f32
    const float* bias = (const float*)d_in[4];   // [64]    f32
    float*       out  = (float*)d_out;           // [B,N,64] f32

    const int N  = NPTS;
    const long long BN = (long long)out_size / HID;   // B*N total points
    const int grid = (int)(BN / BLOCK);

    point_embed_kernel<<<grid, BLOCK>>>(pos, idx, dist, W, bias, out, N);
}

// round 3
// speedup vs baseline: 1.4122x; 1.4122x over previous
#include <cuda_runtime.h>
#include <math.h>

#define BLOCK   128
#define KNN     16
#define HID     64
#define NPTS    65536
#define NBATCH  4

// Scratch: per-batch xyz in AoS float4 (w unused). 4 * 65536 * 16B = 4 MB.
__device__ float4 g_xyz4[NBATCH * NPTS];

// ---------------- Kernel 1: transpose pos [B,3,N] -> float4 [B,N] ----------------
__global__ __launch_bounds__(256) void transpose_pos_kernel(
    const float* __restrict__ pos, int N)
{
    const int i = blockIdx.x * blockDim.x + threadIdx.x;   // 0 .. B*N-1
    const int bb = i / N;
    const int n  = i - bb * N;
    const float* px = pos + (size_t)bb * 3 * N;
    float4 v;
    v.x = __ldg(px + n);
    v.y = __ldg(px + N + n);
    v.z = __ldg(px + 2 * N + n);
    v.w = 0.0f;
    g_xyz4[i] = v;
}

// ---------------- Kernel 2: features + matvec ----------------
__global__ __launch_bounds__(BLOCK) void point_embed_kernel(
    const int*   __restrict__ idx,        // [B,N,K] int32
    const float* __restrict__ dist,       // [B,N,K]
    const float* __restrict__ W,          // [10,64]
    const float* __restrict__ bias,       // [64]
    float* __restrict__ out,              // [B,N,64]
    int N)
{
    __shared__ float feat_s[10][BLOCK];

    const int t = threadIdx.x;
    const long long base_pt = (long long)blockIdx.x * BLOCK;
    const int bb = (int)(base_pt / N);               // block fully inside one batch
    const int n  = (int)(base_pt % N) + t;

    const float4* xb = g_xyz4 + (size_t)bb * N;

    // Self point: single coalesced 16B load
    const float4 s = __ldg(xb + n);

    const int*   ip = idx  + ((size_t)bb * N + n) * KNN;
    const float* dp = dist + ((size_t)bb * N + n) * KNN;

    float mx = -INFINITY, my = -INFINITY, mz = -INFINITY;   // max neighbor
    float nx =  INFINITY, ny =  INFINITY, nz =  INFINITY;   // min neighbor
    float md = -INFINITY;                                    // max dist

    #pragma unroll
    for (int k = 0; k < KNN; k += 4) {
        int4 jj = *reinterpret_cast<const int4*>(ip + k);    // 16B aligned
        const float4 a = __ldg(xb + jj.x);   // one line per neighbor
        const float4 b = __ldg(xb + jj.y);
        const float4 c = __ldg(xb + jj.z);
        const float4 d = __ldg(xb + jj.w);
        mx = fmaxf(fmaxf(fmaxf(mx, a.x), fmaxf(b.x, c.x)), d.x);
        my = fmaxf(fmaxf(fmaxf(my, a.y), fmaxf(b.y, c.y)), d.y);
        mz = fmaxf(fmaxf(fmaxf(mz, a.z), fmaxf(b.z, c.z)), d.z);
        nx = fminf(fminf(fminf(nx, a.x), fminf(b.x, c.x)), d.x);
        ny = fminf(fminf(fminf(ny, a.y), fminf(b.y, c.y)), d.y);
        nz = fminf(fminf(fminf(nz, a.z), fminf(b.z, c.z)), d.z);
    }

    #pragma unroll
    for (int k = 0; k < KNN; k += 4) {
        float4 d4 = *reinterpret_cast<const float4*>(dp + k);
        md = fmaxf(md, fmaxf(fmaxf(d4.x, d4.y), fmaxf(d4.z, d4.w)));
    }

    feat_s[0][t] = s.x;
    feat_s[1][t] = s.y;
    feat_s[2][t] = s.z;
    feat_s[3][t] = mx;
    feat_s[4][t] = my;
    feat_s[5][t] = mz;
    feat_s[6][t] = s.x - nx;   // max(ext - nbr) = ext - min(nbr)
    feat_s[7][t] = s.y - ny;
    feat_s[8][t] = s.z - nz;
    feat_s[9][t] = md;

    __syncthreads();

    // Phase 2: 10x64 matvec, coalesced stores (h = channel, warp writes 128B runs)
    const int h = t & 63;
    float wc[10];
    #pragma unroll
    for (int c = 0; c < 10; c++) wc[c] = __ldg(W + c * HID + h);
    const float bv = __ldg(bias + h);

    float* ob = out + (size_t)base_pt * HID;
    const int p0 = t >> 6;

    #pragma unroll 8
    for (int i = 0; i < BLOCK / 2; i++) {
        const int p = p0 + 2 * i;
        float acc = bv;
        #pragma unroll
        for (int c = 0; c < 10; c++)
            acc = fmaf(feat_s[c][p], wc[c], acc);
        ob[(size_t)p * HID + h] = fmaxf(acc, 0.0f);
    }
}

extern "C" void kernel_launch(void* const* d_in, const int* in_sizes, int n_in,
                              void* d_out, int out_size) {
    const float* pos  = (const float*)d_in[0];   // [B,3,N] f32
    const int*   idx  = (const int*)d_in[1];     // [B,N,K] i32
    const float* dist = (const float*)d_in[2];   // [B,N,K] f32
    const float* W    = (const float*)d_in[3];   // [10,64] f32
    const float* bias = (const float*)d_in[4];   // [64]    f32
    float*       out  = (float*)d_out;           // [B,N,64] f32

    const int N  = NPTS;
    const long long BN = (long long)out_size / HID;   // B*N total points

    transpose_pos_kernel<<<(int)(BN / 256), 256>>>(pos, N);
    point_embed_kernel<<<(int)(BN / BLOCK), BLOCK>>>(idx, dist, W, bias, out, N);
}

// round 4
// speedup vs baseline: 1.8360x; 1.3001x over previous
#include <cuda_runtime.h>
#include <math.h>

#define BLOCK   256
#define KNN     16
#define HID     64
#define NPTS    65536
#define NBATCH  4

// Scratch: per-batch xyz in AoS float4 (w unused). 4 * 65536 * 16B = 4 MB.
__device__ float4 g_xyz4[NBATCH * NPTS];

// ---------------- Kernel 1: transpose pos [B,3,N] -> float4 [B,N] ----------------
__global__ __launch_bounds__(512) void transpose_pos_kernel(
    const float* __restrict__ pos, int N)
{
    const int i = blockIdx.x * 512 + threadIdx.x;   // 0 .. B*N-1
    const int bb = i >> 16;                          // N = 65536
    const int n  = i & (NPTS - 1);
    const float* px = pos + (size_t)bb * 3 * N;
    float4 v;
    v.x = __ldg(px + n);
    v.y = __ldg(px + N + n);
    v.z = __ldg(px + 2 * N + n);
    v.w = 0.0f;
    g_xyz4[i] = v;
}

// ---------------- Kernel 2: features + matvec, warp-autonomous ----------------
__global__ __launch_bounds__(BLOCK) void point_embed_kernel(
    const int*   __restrict__ idx,        // [B,N,K] int32
    const float* __restrict__ dist,       // [B,N,K]
    const float* __restrict__ W,          // [10,64]
    const float* __restrict__ bias,       // [64]
    float* __restrict__ out,              // [B,N,64]
    int N)
{
    // Per-warp private tile: no block-wide barrier anywhere.
    __shared__ float feat_s[BLOCK / 32][10][32];

    const int t = threadIdx.x;
    const int w = t >> 5;
    const int l = t & 31;

    const long long base_pt = (long long)blockIdx.x * BLOCK;   // block inside one batch
    const int bb = (int)(base_pt / N);
    const int n  = (int)(base_pt % N) + t;

    const float4* xb = g_xyz4 + (size_t)bb * N;

    const float4 s = __ldg(xb + n);                 // self point, one 16B load

    const int*   ip = idx  + ((size_t)bb * N + n) * KNN;
    const float* dp = dist + ((size_t)bb * N + n) * KNN;

    float mx = -INFINITY, my = -INFINITY, mz = -INFINITY;   // max neighbor
    float nx =  INFINITY, ny =  INFINITY, nz =  INFINITY;   // min neighbor
    float md = -INFINITY;                                    // max dist

    #pragma unroll
    for (int k = 0; k < KNN; k += 4) {
        int4 jj = *reinterpret_cast<const int4*>(ip + k);    // 16B aligned
        const float4 a = __ldg(xb + jj.x);   // one line per neighbor
        const float4 b = __ldg(xb + jj.y);
        const float4 c = __ldg(xb + jj.z);
        const float4 d = __ldg(xb + jj.w);
        mx = fmaxf(fmaxf(fmaxf(mx, a.x), fmaxf(b.x, c.x)), d.x);
        my = fmaxf(fmaxf(fmaxf(my, a.y), fmaxf(b.y, c.y)), d.y);
        mz = fmaxf(fmaxf(fmaxf(mz, a.z), fmaxf(b.z, c.z)), d.z);
        nx = fminf(fminf(fminf(nx, a.x), fminf(b.x, c.x)), d.x);
        ny = fminf(fminf(fminf(ny, a.y), fminf(b.y, c.y)), d.y);
        nz = fminf(fminf(fminf(nz, a.z), fminf(b.z, c.z)), d.z);
    }

    #pragma unroll
    for (int k = 0; k < KNN; k += 4) {
        float4 d4 = *reinterpret_cast<const float4*>(dp + k);
        md = fmaxf(md, fmaxf(fmaxf(d4.x, d4.y), fmaxf(d4.z, d4.w)));
    }

    feat_s[w][0][l] = s.x;
    feat_s[w][1][l] = s.y;
    feat_s[w][2][l] = s.z;
    feat_s[w][3][l] = mx;
    feat_s[w][4][l] = my;
    feat_s[w][5][l] = mz;
    feat_s[w][6][l] = s.x - nx;   // max(ext - nbr) = ext - min(nbr)
    feat_s[w][7][l] = s.y - ny;
    feat_s[w][8][l] = s.z - nz;
    feat_s[w][9][l] = md;

    __syncwarp();

    // Phase 2 (per-warp): lane l owns channels {2l, 2l+1}; loop 32 points.
    const float2* W2 = reinterpret_cast<const float2*>(W);     // [10][32] float2
    float2 wc[10];
    #pragma unroll
    for (int c = 0; c < 10; c++) wc[c] = __ldg(W2 + c * 32 + l);
    const float2 bv = __ldg(reinterpret_cast<const float2*>(bias) + l);

    float2* ob = reinterpret_cast<float2*>(out + (base_pt + (long long)w * 32) * HID);

    #pragma unroll 8
    for (int p = 0; p < 32; p++) {
        float2 acc = bv;
        #pragma unroll
        for (int c = 0; c < 10; c++) {
            const float f = feat_s[w][c][p];      // warp broadcast, conflict-free
            acc.x = fmaf(f, wc[c].x, acc.x);
            acc.y = fmaf(f, wc[c].y, acc.y);
        }
        acc.x = fmaxf(acc.x, 0.0f);
        acc.y = fmaxf(acc.y, 0.0f);
        ob[p * 32 + l] = acc;                      // warp writes 256B contiguous
    }
}

extern "C" void kernel_launch(void* const* d_in, const int* in_sizes, int n_in,
                              void* d_out, int out_size) {
    const float* pos  = (const float*)d_in[0];   // [B,3,N] f32
    const int*   idx  = (const int*)d_in[1];     // [B,N,K] i32
    const float* dist = (const float*)d_in[2];   // [B,N,K] f32
    const float* W    = (const float*)d_in[3];   // [10,64] f32
    const float* bias = (const float*)d_in[4];   // [64]    f32
    float*       out  = (float*)d_out;           // [B,N,64] f32

    const int N  = NPTS;
    const long long BN = (long long)out_size / HID;   // B*N total points

    transpose_pos_kernel<<<(int)(BN / 512), 512>>>(pos, N);
    point_embed_kernel<<<(int)(BN / BLOCK), BLOCK>>>(idx, dist, W, bias, out, N);
}